// round 2
// baseline (speedup 1.0000x reference)
#include <cuda_runtime.h>
#include <math.h>

#define D_DIM 1536
#define M_TOT 4096          // B*L = 4*1024
#define OUT_DIM 23
#define NGEO 9              // only p[0:9] used

// scratch for h (post-GELU), 4096 x 1536 fp32 = 25 MB
__device__ float g_h[M_TOT * D_DIM];

// ---------------------------------------------------------------------------
// Kernel A: h = GELU(x @ w1^T + b1)
// x: [M_TOT, D_DIM], w1: [D_DIM, D_DIM] (row e contiguous in d)  -> NT GEMM
// 64x64 tile, BK=16, 256 threads, 4x4 microtile per thread.
// ---------------------------------------------------------------------------
__global__ __launch_bounds__(256, 2)
void gemm1_gelu_kernel(const float* __restrict__ x,
                       const float* __restrict__ w1,
                       const float* __restrict__ b1)
{
    constexpr int BM = 64, BN = 64, BK = 16;
    __shared__ float As[BK][BM + 4];
    __shared__ float Bs[BK][BN + 4];

    const int t  = threadIdx.x;
    const int tx = t & 15;           // 0..15 (N direction)
    const int ty = t >> 4;           // 0..15 (M direction)
    const int bm = blockIdx.y * BM;
    const int bn = blockIdx.x * BN;

    // loader mapping: each thread loads one float4 per tile
    const int lr = t >> 2;           // 0..63 row within tile
    const int lk = (t & 3) * 4;      // k offset 0,4,8,12

    const float* pa = x  + (size_t)(bm + lr) * D_DIM + lk;
    const float* pb = w1 + (size_t)(bn + lr) * D_DIM + lk;

    float acc[4][4] = {};

    for (int k0 = 0; k0 < D_DIM; k0 += BK) {
        float4 a4 = *(const float4*)(pa + k0);
        float4 b4 = *(const float4*)(pb + k0);
        __syncthreads();
        As[lk + 0][lr] = a4.x; As[lk + 1][lr] = a4.y;
        As[lk + 2][lr] = a4.z; As[lk + 3][lr] = a4.w;
        Bs[lk + 0][lr] = b4.x; Bs[lk + 1][lr] = b4.y;
        Bs[lk + 2][lr] = b4.z; Bs[lk + 3][lr] = b4.w;
        __syncthreads();

        #pragma unroll
        for (int k = 0; k < BK; k++) {
            float a[4], b[4];
            #pragma unroll
            for (int i = 0; i < 4; i++) a[i] = As[k][ty + i * 16];
            #pragma unroll
            for (int j = 0; j < 4; j++) b[j] = Bs[k][tx + j * 16];
            #pragma unroll
            for (int i = 0; i < 4; i++)
                #pragma unroll
                for (int j = 0; j < 4; j++)
                    acc[i][j] = fmaf(a[i], b[j], acc[i][j]);
        }
    }

    #pragma unroll
    for (int i = 0; i < 4; i++) {
        const int m = bm + ty + i * 16;
        #pragma unroll
        for (int j = 0; j < 4; j++) {
            const int e = bn + tx + j * 16;
            float v = acc[i][j] + b1[e];
            // exact GELU: 0.5 * v * (1 + erf(v / sqrt(2)))
            float g = 0.5f * v * (1.0f + erff(v * 0.70710678118654752440f));
            g_h[(size_t)m * D_DIM + e] = g;
        }
    }
}

// ---------------------------------------------------------------------------
// Kernel B: per-token LayerNorm -> p[0:9] = hnorm @ w2^T + b2 -> geometry
// one block (256 threads) per token row.
// ---------------------------------------------------------------------------
__device__ __forceinline__ float block_reduce_sum(float v, float* red)
{
    #pragma unroll
    for (int o = 16; o; o >>= 1) v += __shfl_xor_sync(0xFFFFFFFFu, v, o);
    const int lane = threadIdx.x & 31;
    const int w    = threadIdx.x >> 5;
    if (lane == 0) red[w] = v;
    __syncthreads();
    float r = (threadIdx.x < 8) ? red[threadIdx.x] : 0.0f;
    if (threadIdx.x < 32) {
        #pragma unroll
        for (int o = 4; o; o >>= 1) r += __shfl_xor_sync(0xFFu, r, o);
        if (threadIdx.x == 0) red[0] = r;
    }
    __syncthreads();
    float out = red[0];
    __syncthreads();   // red reusable afterwards
    return out;
}

__constant__ float c_bb[3][3] = {
    {-0.525f, 1.363f, 0.0f},
    { 0.0f,   0.0f,   0.0f},
    { 1.526f, 0.0f,   0.0f}
};

__global__ __launch_bounds__(256, 4)
void ln_head_kernel(const float* __restrict__ ln_g,
                    const float* __restrict__ ln_b,
                    const float* __restrict__ w2,
                    const float* __restrict__ b2,
                    const float* __restrict__ affine,
                    const int*   __restrict__ mask,     // nonzero == true
                    float* __restrict__ out)
{
    const int row = blockIdx.x;
    const int tid = threadIdx.x;
    constexpr int T = 256;
    constexpr int PER = D_DIM / T;   // 6

    __shared__ float sh[D_DIM];
    __shared__ float red[32];
    __shared__ float p[12];

    const float* hrow = g_h + (size_t)row * D_DIM;

    float local[PER];
    float s = 0.0f;
    #pragma unroll
    for (int i = 0; i < PER; i++) {
        float v = hrow[tid + i * T];
        local[i] = v;
        s += v;
    }
    const float mu = block_reduce_sum(s, red) * (1.0f / D_DIM);

    float s2 = 0.0f;
    #pragma unroll
    for (int i = 0; i < PER; i++) {
        float d = local[i] - mu;
        s2 += d * d;
    }
    const float var = block_reduce_sum(s2, red) * (1.0f / D_DIM);
    const float inv = rsqrtf(var + 1e-5f);

    #pragma unroll
    for (int i = 0; i < PER; i++) {
        const int idx = tid + i * T;
        sh[idx] = (local[i] - mu) * inv * ln_g[idx] + ln_b[idx];
    }
    __syncthreads();

    // p[o] for o in 0..8 : warp-per-output (warp 0 also does o=8)
    const int warp = tid >> 5, lane = tid & 31;
    for (int o = warp; o < NGEO; o += 8) {
        const float* wr = w2 + (size_t)o * D_DIM;
        float acc = 0.0f;
        for (int d = lane; d < D_DIM; d += 32)
            acc = fmaf(sh[d], wr[d], acc);
        #pragma unroll
        for (int off = 16; off; off >>= 1) acc += __shfl_xor_sync(0xFFFFFFFFu, acc, off);
        if (lane == 0) p[o] = acc + b2[o];
    }
    __syncthreads();

    if (tid == 0) {
        float trans[3], xv[3], yv[3];
        #pragma unroll
        for (int i = 0; i < 3; i++) {
            trans[i] = p[i] * 10.0f;
            xv[i]    = p[3 + i];
            yv[i]    = p[6 + i];
        }
        float xn = sqrtf(xv[0]*xv[0] + xv[1]*xv[1] + xv[2]*xv[2]) + 1e-5f;
        float yn = sqrtf(yv[0]*yv[0] + yv[1]*yv[1] + yv[2]*yv[2]) + 1e-5f;
        #pragma unroll
        for (int i = 0; i < 3; i++) { xv[i] /= xn; yv[i] /= yn; }

        // trans - neg_x = -xv ; p_xy - trans = yv
        float ax[3] = { -xv[0], -xv[1], -xv[2] };   // x_axis
        // Gram-Schmidt
        float n0 = rsqrtf(ax[0]*ax[0] + ax[1]*ax[1] + ax[2]*ax[2] + 1e-12f);
        float e0[3] = { ax[0]*n0, ax[1]*n0, ax[2]*n0 };
        float c = e0[0]*yv[0] + e0[1]*yv[1] + e0[2]*yv[2];
        float e1[3] = { yv[0] - e0[0]*c, yv[1] - e0[1]*c, yv[2] - e0[2]*c };
        float n1 = rsqrtf(e1[0]*e1[0] + e1[1]*e1[1] + e1[2]*e1[2] + 1e-12f);
        e1[0] *= n1; e1[1] *= n1; e1[2] *= n1;
        float e2[3] = { e0[1]*e1[2] - e0[2]*e1[1],
                        e0[2]*e1[0] - e0[0]*e1[2],
                        e0[0]*e1[1] - e0[1]*e1[0] };

        // Ru columns = e0, e1, e2
        float Ru[3][3] = {
            { e0[0], e1[0], e2[0] },
            { e0[1], e1[1], e2[1] },
            { e0[2], e1[2], e2[2] }
        };
        float tu[3] = { trans[0], trans[1], trans[2] };

        const bool m = (mask[row] != 0);
        if (!m) {
            #pragma unroll
            for (int i = 0; i < 3; i++) {
                #pragma unroll
                for (int j = 0; j < 3; j++) Ru[i][j] = (i == j) ? 1.0f : 0.0f;
                tu[i] = 0.0f;
            }
        }

        const float* af = affine + (size_t)row * 12;
        float R0[3][3], t0[3];
        #pragma unroll
        for (int i = 0; i < 3; i++) {
            #pragma unroll
            for (int j = 0; j < 3; j++) R0[i][j] = af[i * 3 + j];
            t0[i] = af[9 + i];
        }

        float R[3][3], tt[3];
        #pragma unroll
        for (int i = 0; i < 3; i++) {
            #pragma unroll
            for (int j = 0; j < 3; j++) {
                float acc = 0.0f;
                #pragma unroll
                for (int k = 0; k < 3; k++) acc = fmaf(R0[i][k], Ru[k][j], acc);
                R[i][j] = acc;
            }
            float ta = t0[i];
            #pragma unroll
            for (int j = 0; j < 3; j++) ta = fmaf(R0[i][j], tu[j], ta);
            tt[i] = ta;
        }

        // affine_out: [M_TOT, 12]
        float* ao = out + (size_t)row * 12;
        #pragma unroll
        for (int i = 0; i < 3; i++)
            #pragma unroll
            for (int j = 0; j < 3; j++) ao[i * 3 + j] = R[i][j];
        #pragma unroll
        for (int i = 0; i < 3; i++) ao[9 + i] = tt[i];

        // pred_xyz: [M_TOT, 3(atom a), 3(coord i)] appended after affine_out
        float* po = out + (size_t)M_TOT * 12 + (size_t)row * 9;
        #pragma unroll
        for (int a = 0; a < 3; a++) {
            #pragma unroll
            for (int i = 0; i < 3; i++) {
                float v = tt[i];
                #pragma unroll
                for (int j = 0; j < 3; j++) v = fmaf(R[i][j], c_bb[a][j], v);
                po[a * 3 + i] = v;
            }
        }
    }
}

// ---------------------------------------------------------------------------
extern "C" void kernel_launch(void* const* d_in, const int* in_sizes, int n_in,
                              void* d_out, int out_size)
{
    const float* x      = (const float*)d_in[0];
    const float* affine = (const float*)d_in[1];
    const int*   amask  = (const int*)  d_in[2];   // nonzero test works for int32 or f32 bits
    const float* w1     = (const float*)d_in[3];
    const float* b1     = (const float*)d_in[4];
    const float* ln_g   = (const float*)d_in[5];
    const float* ln_b   = (const float*)d_in[6];
    const float* w2     = (const float*)d_in[7];
    const float* b2     = (const float*)d_in[8];
    float* out = (float*)d_out;

    dim3 gridA(D_DIM / 64, M_TOT / 64);
    gemm1_gelu_kernel<<<gridA, 256>>>(x, w1, b1);

    ln_head_kernel<<<M_TOT, 256>>>(ln_g, ln_b, w2, b2, affine, amask, out);
}

// round 4
// speedup vs baseline: 3.1607x; 3.1607x over previous
#include <cuda_runtime.h>
#include <cuda_bf16.h>
#include <math.h>
#include <cstdint>

#define D_DIM 1536
#define M_TOT 4096          // B*L
#define K3    4608          // 3 * D_DIM (hi|lo|hi split along K)
#define NCHUNK 72           // K3 / 64
#define TM 128
#define TN 128
#define NGEO 9

// scratch (device globals — no allocation allowed)
__device__ __nv_bfloat16 g_A[(size_t)M_TOT * K3];   // [M, K3]  = [hi | lo | hi]
__device__ __nv_bfloat16 g_B[(size_t)D_DIM * K3];   // [N, K3]  = [hi | hi | lo]
__device__ float         g_h[(size_t)M_TOT * D_DIM];

// ---------------------------------------------------------------------------
// split-to-bf16 conversion kernels
// ---------------------------------------------------------------------------
__global__ void conv_x_kernel(const float* __restrict__ x)
{
    int i = blockIdx.x * blockDim.x + threadIdx.x;
    int stride = gridDim.x * blockDim.x;
    for (; i < M_TOT * D_DIM; i += stride) {
        int m = i / D_DIM, d = i - m * D_DIM;
        float v = x[i];
        __nv_bfloat16 hi = __float2bfloat16(v);
        __nv_bfloat16 lo = __float2bfloat16(v - __bfloat162float(hi));
        size_t base = (size_t)m * K3;
        g_A[base + d]            = hi;
        g_A[base + D_DIM + d]    = lo;
        g_A[base + 2*D_DIM + d]  = hi;
    }
}

__global__ void conv_w_kernel(const float* __restrict__ w1)
{
    int i = blockIdx.x * blockDim.x + threadIdx.x;
    int stride = gridDim.x * blockDim.x;
    for (; i < D_DIM * D_DIM; i += stride) {
        int e = i / D_DIM, d = i - e * D_DIM;
        float v = w1[i];
        __nv_bfloat16 hi = __float2bfloat16(v);
        __nv_bfloat16 lo = __float2bfloat16(v - __bfloat162float(hi));
        size_t base = (size_t)e * K3;
        g_B[base + d]            = hi;
        g_B[base + D_DIM + d]    = hi;
        g_B[base + 2*D_DIM + d]  = lo;
    }
}

// ---------------------------------------------------------------------------
// HMMA (mma.sync bf16) GEMM: g_h = GELU( A' @ B'^T + b1 )
// ---------------------------------------------------------------------------
#define SWZ(o) ((o) ^ (((o) >> 3) & 0x70))

__device__ __forceinline__ uint32_t s2u(const void* p) {
    uint32_t a;
    asm("{ .reg .u64 t; cvta.to.shared.u64 t, %1; cvt.u32.u64 %0, t; }"
        : "=r"(a) : "l"(p));
    return a;
}
__device__ __forceinline__ void cp16(uint32_t dst, const void* src) {
    asm volatile("cp.async.cg.shared.global [%0], [%1], 16;\n"
                 :: "r"(dst), "l"(src));
}
__device__ __forceinline__ void ldm4(uint32_t* r, uint32_t addr) {
    asm volatile("ldmatrix.sync.aligned.m8n8.x4.shared.b16 {%0,%1,%2,%3}, [%4];"
                 : "=r"(r[0]), "=r"(r[1]), "=r"(r[2]), "=r"(r[3]) : "r"(addr));
}
__device__ __forceinline__ void mma16816(float* c, const uint32_t* a, const uint32_t* b) {
    asm volatile("mma.sync.aligned.m16n8k16.row.col.f32.bf16.bf16.f32 "
                 "{%0,%1,%2,%3}, {%4,%5,%6,%7}, {%8,%9}, {%0,%1,%2,%3};"
                 : "+f"(c[0]), "+f"(c[1]), "+f"(c[2]), "+f"(c[3])
                 : "r"(a[0]), "r"(a[1]), "r"(a[2]), "r"(a[3]),
                   "r"(b[0]), "r"(b[1]));
}

static constexpr int TILE_B = TM * 128;                 // 16 KB per operand/stage
static constexpr int SMEM_BYTES = 4 * TILE_B + 1024;    // 2 stages x (A,B) + align

__global__ __launch_bounds__(256)
void gemm_mma_kernel(const float* __restrict__ b1)
{
    extern __shared__ char smem[];
    const uint32_t sb = (s2u(smem) + 1023) & ~1023u;

    const int tid  = threadIdx.x;
    const int wid  = tid >> 5, lane = tid & 31;
    const int wm   = wid & 1;          // 2 warps in M
    const int wn   = wid >> 1;         // 4 warps in N
    const int bn   = blockIdx.x * TN;
    const int bm   = blockIdx.y * TM;

    const uint32_t A_OFF[2] = { sb,              sb + TILE_B };
    const uint32_t B_OFF[2] = { sb + 2*TILE_B,   sb + 3*TILE_B };

    // ---- per-lane ldmatrix address components (offsets within a tile) ----
    // A (m-tiles): lane -> row = wm*64 + i*16 + (lane&15); k-half = (lane>>4)*16B
    uint32_t a_row[4], a_xr[4];
    #pragma unroll
    for (int i = 0; i < 4; i++) {
        int row = wm * 64 + i * 16 + (lane & 15);
        a_row[i] = row * 128;
        a_xr[i]  = (row & 7) << 4;
    }
    const uint32_t a_kh = (lane >> 4) * 16;

    // B (n-pairs): lane -> nrow = wn*32 + j2*16 + (lane&7) + ((lane>>4)&1)*8 ;
    //              k-half = ((lane>>3)&1)*16B
    uint32_t b_row[2], b_xr[2];
    #pragma unroll
    for (int j2 = 0; j2 < 2; j2++) {
        int row = wn * 32 + j2 * 16 + (lane & 7) + ((lane >> 4) & 1) * 8;
        b_row[j2] = row * 128;
        b_xr[j2]  = (row & 7) << 4;
    }
    const uint32_t b_kh = ((lane >> 3) & 1) * 16;

    auto load_stage = [&](int s, int k0) {
        #pragma unroll
        for (int i = 0; i < 4; i++) {
            int u = tid + i * 256;           // 0..1023
            int r = u >> 3, c8 = u & 7;
            cp16(A_OFF[s] + SWZ(r * 128 + c8 * 16),
                 g_A + (size_t)(bm + r) * K3 + k0 + c8 * 8);
            cp16(B_OFF[s] + SWZ(r * 128 + c8 * 16),
                 g_B + (size_t)(bn + r) * K3 + k0 + c8 * 8);
        }
    };

    float acc[4][4][4] = {};   // [mtile][ntile][c0..c3]

    load_stage(0, 0);
    asm volatile("cp.async.commit_group;" ::: "memory");

    for (int ch = 0; ch < NCHUNK; ch++) {
        const int cur = ch & 1, nxt = cur ^ 1;
        if (ch + 1 < NCHUNK) {
            load_stage(nxt, (ch + 1) * 64);
            asm volatile("cp.async.commit_group;" ::: "memory");
            asm volatile("cp.async.wait_group 1;" ::: "memory");
        } else {
            asm volatile("cp.async.wait_group 0;" ::: "memory");
        }
        __syncthreads();

        const uint32_t Ab = A_OFF[cur], Bb = B_OFF[cur];
        #pragma unroll
        for (int ks = 0; ks < 4; ks++) {
            const uint32_t kb = ks * 32;
            uint32_t af[4][4], bf[2][4];
            #pragma unroll
            for (int i = 0; i < 4; i++)
                ldm4(af[i], Ab + a_row[i] + ((kb + a_kh) ^ a_xr[i]));
            #pragma unroll
            for (int j2 = 0; j2 < 2; j2++)
                ldm4(bf[j2], Bb + b_row[j2] + ((kb + b_kh) ^ b_xr[j2]));

            #pragma unroll
            for (int i = 0; i < 4; i++) {
                #pragma unroll
                for (int j = 0; j < 4; j++)
                    mma16816(acc[i][j], af[i], bf[j >> 1] + (j & 1) * 2);
            }
        }
        __syncthreads();
    }

    // ---- epilogue: bias + exact GELU from fragments ----
    const int r0 = lane >> 2;             // 0..7
    const int c0 = (lane & 3) * 2;        // 0,2,4,6
    #pragma unroll
    for (int i = 0; i < 4; i++) {
        const int m0 = bm + wm * 64 + i * 16 + r0;
        #pragma unroll
        for (int j = 0; j < 4; j++) {
            const int col = bn + wn * 32 + j * 8 + c0;
            const float bb0 = __ldg(&b1[col]);
            const float bb1 = __ldg(&b1[col + 1]);
            #pragma unroll
            for (int half = 0; half < 2; half++) {
                const int m = m0 + half * 8;
                float v0 = acc[i][j][half * 2 + 0] + bb0;
                float v1 = acc[i][j][half * 2 + 1] + bb1;
                float g0 = 0.5f * v0 * (1.0f + erff(v0 * 0.70710678118654752440f));
                float g1 = 0.5f * v1 * (1.0f + erff(v1 * 0.70710678118654752440f));
                *(float2*)(g_h + (size_t)m * D_DIM + col) = make_float2(g0, g1);
            }
        }
    }
}

// ---------------------------------------------------------------------------
// Kernel B: per-token LayerNorm -> p[0:9] -> geometry
// ---------------------------------------------------------------------------
__device__ __forceinline__ float block_reduce_sum(float v, float* red)
{
    #pragma unroll
    for (int o = 16; o; o >>= 1) v += __shfl_xor_sync(0xFFFFFFFFu, v, o);
    const int lane = threadIdx.x & 31;
    const int w    = threadIdx.x >> 5;
    if (lane == 0) red[w] = v;
    __syncthreads();
    float r = (threadIdx.x < 8) ? red[threadIdx.x] : 0.0f;
    if (threadIdx.x < 32) {
        #pragma unroll
        for (int o = 4; o; o >>= 1) r += __shfl_xor_sync(0xFFu, r, o);
        if (threadIdx.x == 0) red[0] = r;
    }
    __syncthreads();
    float out = red[0];
    __syncthreads();
    return out;
}

__constant__ float c_bb[3][3] = {
    {-0.525f, 1.363f, 0.0f},
    { 0.0f,   0.0f,   0.0f},
    { 1.526f, 0.0f,   0.0f}
};

__global__ __launch_bounds__(256, 4)
void ln_head_kernel(const float* __restrict__ ln_g,
                    const float* __restrict__ ln_b,
                    const float* __restrict__ w2,
                    const float* __restrict__ b2,
                    const float* __restrict__ affine,
                    const int*   __restrict__ mask,
                    float* __restrict__ out)
{
    const int row = blockIdx.x;
    const int tid = threadIdx.x;
    constexpr int T = 256;
    constexpr int PER = D_DIM / T;

    __shared__ float sh[D_DIM];
    __shared__ float red[32];
    __shared__ float p[12];

    const float* hrow = g_h + (size_t)row * D_DIM;

    float local[PER];
    float s = 0.0f;
    #pragma unroll
    for (int i = 0; i < PER; i++) {
        float v = hrow[tid + i * T];
        local[i] = v;
        s += v;
    }
    const float mu = block_reduce_sum(s, red) * (1.0f / D_DIM);

    float s2 = 0.0f;
    #pragma unroll
    for (int i = 0; i < PER; i++) {
        float d = local[i] - mu;
        s2 += d * d;
    }
    const float var = block_reduce_sum(s2, red) * (1.0f / D_DIM);
    const float inv = rsqrtf(var + 1e-5f);

    #pragma unroll
    for (int i = 0; i < PER; i++) {
        const int idx = tid + i * T;
        sh[idx] = (local[i] - mu) * inv * ln_g[idx] + ln_b[idx];
    }
    __syncthreads();

    const int warp = tid >> 5, lane = tid & 31;
    for (int o = warp; o < NGEO; o += 8) {
        const float* wr = w2 + (size_t)o * D_DIM;
        float acc = 0.0f;
        for (int d = lane; d < D_DIM; d += 32)
            acc = fmaf(sh[d], wr[d], acc);
        #pragma unroll
        for (int off = 16; off; off >>= 1) acc += __shfl_xor_sync(0xFFFFFFFFu, acc, off);
        if (lane == 0) p[o] = acc + b2[o];
    }
    __syncthreads();

    if (tid == 0) {
        float trans[3], xv[3], yv[3];
        #pragma unroll
        for (int i = 0; i < 3; i++) {
            trans[i] = p[i] * 10.0f;
            xv[i]    = p[3 + i];
            yv[i]    = p[6 + i];
        }
        float xn = sqrtf(xv[0]*xv[0] + xv[1]*xv[1] + xv[2]*xv[2]) + 1e-5f;
        float yn = sqrtf(yv[0]*yv[0] + yv[1]*yv[1] + yv[2]*yv[2]) + 1e-5f;
        #pragma unroll
        for (int i = 0; i < 3; i++) { xv[i] /= xn; yv[i] /= yn; }

        float ax[3] = { -xv[0], -xv[1], -xv[2] };
        float n0 = rsqrtf(ax[0]*ax[0] + ax[1]*ax[1] + ax[2]*ax[2] + 1e-12f);
        float e0[3] = { ax[0]*n0, ax[1]*n0, ax[2]*n0 };
        float c = e0[0]*yv[0] + e0[1]*yv[1] + e0[2]*yv[2];
        float e1[3] = { yv[0] - e0[0]*c, yv[1] - e0[1]*c, yv[2] - e0[2]*c };
        float n1 = rsqrtf(e1[0]*e1[0] + e1[1]*e1[1] + e1[2]*e1[2] + 1e-12f);
        e1[0] *= n1; e1[1] *= n1; e1[2] *= n1;
        float e2[3] = { e0[1]*e1[2] - e0[2]*e1[1],
                        e0[2]*e1[0] - e0[0]*e1[2],
                        e0[0]*e1[1] - e0[1]*e1[0] };

        float Ru[3][3] = {
            { e0[0], e1[0], e2[0] },
            { e0[1], e1[1], e2[1] },
            { e0[2], e1[2], e2[2] }
        };
        float tu[3] = { trans[0], trans[1], trans[2] };

        const bool m = (mask[row] != 0);
        if (!m) {
            #pragma unroll
            for (int i = 0; i < 3; i++) {
                #pragma unroll
                for (int j = 0; j < 3; j++) Ru[i][j] = (i == j) ? 1.0f : 0.0f;
                tu[i] = 0.0f;
            }
        }

        const float* af = affine + (size_t)row * 12;
        float R0[3][3], t0[3];
        #pragma unroll
        for (int i = 0; i < 3; i++) {
            #pragma unroll
            for (int j = 0; j < 3; j++) R0[i][j] = af[i * 3 + j];
            t0[i] = af[9 + i];
        }

        float R[3][3], tt[3];
        #pragma unroll
        for (int i = 0; i < 3; i++) {
            #pragma unroll
            for (int j = 0; j < 3; j++) {
                float acc = 0.0f;
                #pragma unroll
                for (int k = 0; k < 3; k++) acc = fmaf(R0[i][k], Ru[k][j], acc);
                R[i][j] = acc;
            }
            float ta = t0[i];
            #pragma unroll
            for (int j = 0; j < 3; j++) ta = fmaf(R0[i][j], tu[j], ta);
            tt[i] = ta;
        }

        float* ao = out + (size_t)row * 12;
        #pragma unroll
        for (int i = 0; i < 3; i++)
            #pragma unroll
            for (int j = 0; j < 3; j++) ao[i * 3 + j] = R[i][j];
        #pragma unroll
        for (int i = 0; i < 3; i++) ao[9 + i] = tt[i];

        float* po = out + (size_t)M_TOT * 12 + (size_t)row * 9;
        #pragma unroll
        for (int a = 0; a < 3; a++) {
            #pragma unroll
            for (int i = 0; i < 3; i++) {
                float v = tt[i];
                #pragma unroll
                for (int j = 0; j < 3; j++) v = fmaf(R[i][j], c_bb[a][j], v);
                po[a * 3 + i] = v;
            }
        }
    }
}

// ---------------------------------------------------------------------------
extern "C" void kernel_launch(void* const* d_in, const int* in_sizes, int n_in,
                              void* d_out, int out_size)
{
    const float* x      = (const float*)d_in[0];
    const float* affine = (const float*)d_in[1];
    const int*   amask  = (const int*)  d_in[2];
    const float* w1     = (const float*)d_in[3];
    const float* b1     = (const float*)d_in[4];
    const float* ln_g   = (const float*)d_in[5];
    const float* ln_b   = (const float*)d_in[6];
    const float* w2     = (const float*)d_in[7];
    const float* b2     = (const float*)d_in[8];
    float* out = (float*)d_out;

    cudaFuncSetAttribute(gemm_mma_kernel,
                         cudaFuncAttributeMaxDynamicSharedMemorySize, SMEM_BYTES);

    conv_x_kernel<<<4096, 256>>>(x);
    conv_w_kernel<<<2304, 256>>>(w1);

    dim3 grid(D_DIM / TN, M_TOT / TM);   // (12, 32)
    gemm_mma_kernel<<<grid, 256, SMEM_BYTES>>>(b1);

    ln_head_kernel<<<M_TOT, 256>>>(ln_g, ln_b, w2, b2, affine, amask, out);
}

// round 5
// speedup vs baseline: 3.5460x; 1.1219x over previous
#include <cuda_runtime.h>
#include <cuda_bf16.h>
#include <math.h>
#include <cstdint>

#define D_DIM 1536
#define M_TOT 4096          // B*L
#define K2    3072          // 2 * D_DIM : [hi | lo]
#define NCH   24            // 1536 / 64
#define TM 128
#define TN 128
#define NGEO 9

// scratch (device globals — no allocation allowed)
__device__ __nv_bfloat16 g_A[(size_t)M_TOT * K2];   // [M, K2] = [hi | lo]
__device__ __nv_bfloat16 g_B[(size_t)D_DIM * K2];   // [N, K2] = [hi | lo]
__device__ float         g_h[(size_t)M_TOT * D_DIM];

// ---------------------------------------------------------------------------
// split-to-bf16 conversion kernels
// ---------------------------------------------------------------------------
__global__ void conv_x_kernel(const float* __restrict__ x)
{
    int i = blockIdx.x * blockDim.x + threadIdx.x;
    int stride = gridDim.x * blockDim.x;
    for (; i < M_TOT * D_DIM; i += stride) {
        int m = i / D_DIM, d = i - m * D_DIM;
        float v = x[i];
        __nv_bfloat16 hi = __float2bfloat16(v);
        __nv_bfloat16 lo = __float2bfloat16(v - __bfloat162float(hi));
        size_t base = (size_t)m * K2;
        g_A[base + d]          = hi;
        g_A[base + D_DIM + d]  = lo;
    }
}

__global__ void conv_w_kernel(const float* __restrict__ w1)
{
    int i = blockIdx.x * blockDim.x + threadIdx.x;
    int stride = gridDim.x * blockDim.x;
    for (; i < D_DIM * D_DIM; i += stride) {
        int e = i / D_DIM, d = i - e * D_DIM;
        float v = w1[i];
        __nv_bfloat16 hi = __float2bfloat16(v);
        __nv_bfloat16 lo = __float2bfloat16(v - __bfloat162float(hi));
        size_t base = (size_t)e * K2;
        g_B[base + d]          = hi;
        g_B[base + D_DIM + d]  = lo;
    }
}

// ---------------------------------------------------------------------------
// HMMA GEMM with in-register hi/lo sharing:
//   acc += A_hi·B_hi + A_lo·B_hi + A_hi·B_lo      (lo·lo dropped, O(2^-18))
// ---------------------------------------------------------------------------
#define SWZ(o) ((o) ^ (((o) >> 3) & 0x70))

__device__ __forceinline__ uint32_t s2u(const void* p) {
    uint32_t a;
    asm("{ .reg .u64 t; cvta.to.shared.u64 t, %1; cvt.u32.u64 %0, t; }"
        : "=r"(a) : "l"(p));
    return a;
}
__device__ __forceinline__ void cp16(uint32_t dst, const void* src) {
    asm volatile("cp.async.cg.shared.global [%0], [%1], 16;\n"
                 :: "r"(dst), "l"(src));
}
__device__ __forceinline__ void ldm4(uint32_t* r, uint32_t addr) {
    asm volatile("ldmatrix.sync.aligned.m8n8.x4.shared.b16 {%0,%1,%2,%3}, [%4];"
                 : "=r"(r[0]), "=r"(r[1]), "=r"(r[2]), "=r"(r[3]) : "r"(addr));
}
__device__ __forceinline__ void mma16816(float* c, const uint32_t* a, const uint32_t* b) {
    asm volatile("mma.sync.aligned.m16n8k16.row.col.f32.bf16.bf16.f32 "
                 "{%0,%1,%2,%3}, {%4,%5,%6,%7}, {%8,%9}, {%0,%1,%2,%3};"
                 : "+f"(c[0]), "+f"(c[1]), "+f"(c[2]), "+f"(c[3])
                 : "r"(a[0]), "r"(a[1]), "r"(a[2]), "r"(a[3]),
                   "r"(b[0]), "r"(b[1]));
}

static constexpr int TILE_B  = TM * 128;               // 16 KB per tile (128 rows x 128B)
static constexpr int STAGE_B = 4 * TILE_B;             // AH, AL, BH, BL = 64 KB
static constexpr int SMEM_BYTES = 2 * STAGE_B + 1024;  // 2 stages + align

__global__ __launch_bounds__(256)
void gemm_mma_kernel(const float* __restrict__ b1)
{
    extern __shared__ char smem[];
    const uint32_t sb = (s2u(smem) + 1023) & ~1023u;

    const int tid  = threadIdx.x;
    const int wid  = tid >> 5, lane = tid & 31;
    const int wm   = wid & 1;          // 2 warps in M (64 rows each)
    const int wn   = wid >> 1;         // 4 warps in N (32 cols each)
    const int bn   = blockIdx.x * TN;
    const int bm   = blockIdx.y * TM;

    // stage s base; tile offsets: AH=0, AL=1, BH=2, BL=3 (x 16KB)
    const uint32_t STG[2] = { sb, sb + STAGE_B };

    // ---- per-lane ldmatrix address components ----
    uint32_t a_row[4], a_xr[4];
    #pragma unroll
    for (int i = 0; i < 4; i++) {
        int row = wm * 64 + i * 16 + (lane & 15);
        a_row[i] = row * 128;
        a_xr[i]  = (row & 7) << 4;
    }
    const uint32_t a_kh = (lane >> 4) * 16;

    uint32_t b_row[2], b_xr[2];
    #pragma unroll
    for (int j2 = 0; j2 < 2; j2++) {
        int row = wn * 32 + j2 * 16 + (lane & 7) + ((lane >> 4) & 1) * 8;
        b_row[j2] = row * 128;
        b_xr[j2]  = (row & 7) << 4;
    }
    const uint32_t b_kh = ((lane >> 3) & 1) * 16;

    auto load_stage = [&](int s, int k0) {
        const uint32_t st = STG[s];
        #pragma unroll
        for (int i = 0; i < 4; i++) {
            int u  = tid + i * 256;          // 0..1023
            int r  = u >> 3, c8 = u & 7;
            uint32_t dsw = SWZ(r * 128 + c8 * 16);
            const __nv_bfloat16* arow = g_A + (size_t)(bm + r) * K2 + k0 + c8 * 8;
            const __nv_bfloat16* brow = g_B + (size_t)(bn + r) * K2 + k0 + c8 * 8;
            cp16(st              + dsw, arow);           // A_hi
            cp16(st +     TILE_B + dsw, arow + D_DIM);   // A_lo
            cp16(st + 2 * TILE_B + dsw, brow);           // B_hi
            cp16(st + 3 * TILE_B + dsw, brow + D_DIM);   // B_lo
        }
    };

    float acc[4][4][4] = {};   // [mtile][ntile][c]

    load_stage(0, 0);
    asm volatile("cp.async.commit_group;" ::: "memory");

    for (int ch = 0; ch < NCH; ch++) {
        const int cur = ch & 1, nxt = cur ^ 1;
        if (ch + 1 < NCH) {
            load_stage(nxt, (ch + 1) * 64);
            asm volatile("cp.async.commit_group;" ::: "memory");
            asm volatile("cp.async.wait_group 1;" ::: "memory");
        } else {
            asm volatile("cp.async.wait_group 0;" ::: "memory");
        }
        __syncthreads();

        const uint32_t AH = STG[cur];
        const uint32_t AL = AH + TILE_B;
        const uint32_t BH = AH + 2 * TILE_B;
        const uint32_t BL = AH + 3 * TILE_B;

        #pragma unroll
        for (int ks = 0; ks < 4; ks++) {
            const uint32_t kb = ks * 32;
            uint32_t ah[4][4], al[4][4], bh[2][4], bl[2][4];
            #pragma unroll
            for (int i = 0; i < 4; i++) {
                uint32_t off = a_row[i] + ((kb + a_kh) ^ a_xr[i]);
                ldm4(ah[i], AH + off);
                ldm4(al[i], AL + off);
            }
            #pragma unroll
            for (int j2 = 0; j2 < 2; j2++) {
                uint32_t off = b_row[j2] + ((kb + b_kh) ^ b_xr[j2]);
                ldm4(bh[j2], BH + off);
                ldm4(bl[j2], BL + off);
            }
            #pragma unroll
            for (int i = 0; i < 4; i++) {
                #pragma unroll
                for (int j = 0; j < 4; j++) {
                    const uint32_t* bhp = bh[j >> 1] + (j & 1) * 2;
                    const uint32_t* blp = bl[j >> 1] + (j & 1) * 2;
                    mma16816(acc[i][j], ah[i], bhp);
                    mma16816(acc[i][j], al[i], bhp);
                    mma16816(acc[i][j], ah[i], blp);
                }
            }
        }
        __syncthreads();
    }

    // ---- epilogue: bias + exact GELU from fragments ----
    const int r0 = lane >> 2;
    const int c0 = (lane & 3) * 2;
    #pragma unroll
    for (int i = 0; i < 4; i++) {
        const int m0 = bm + wm * 64 + i * 16 + r0;
        #pragma unroll
        for (int j = 0; j < 4; j++) {
            const int col = bn + wn * 32 + j * 8 + c0;
            const float bb0 = __ldg(&b1[col]);
            const float bb1 = __ldg(&b1[col + 1]);
            #pragma unroll
            for (int half = 0; half < 2; half++) {
                const int m = m0 + half * 8;
                float v0 = acc[i][j][half * 2 + 0] + bb0;
                float v1 = acc[i][j][half * 2 + 1] + bb1;
                float g0 = 0.5f * v0 * (1.0f + erff(v0 * 0.70710678118654752440f));
                float g1 = 0.5f * v1 * (1.0f + erff(v1 * 0.70710678118654752440f));
                *(float2*)(g_h + (size_t)m * D_DIM + col) = make_float2(g0, g1);
            }
        }
    }
}

// ---------------------------------------------------------------------------
// Kernel B: per-token LayerNorm -> p[0:9] -> geometry  (vectorized loads)
// ---------------------------------------------------------------------------
__device__ __forceinline__ float block_reduce_sum(float v, float* red)
{
    #pragma unroll
    for (int o = 16; o; o >>= 1) v += __shfl_xor_sync(0xFFFFFFFFu, v, o);
    const int lane = threadIdx.x & 31;
    const int w    = threadIdx.x >> 5;
    if (lane == 0) red[w] = v;
    __syncthreads();
    float r = (threadIdx.x < 8) ? red[threadIdx.x] : 0.0f;
    if (threadIdx.x < 32) {
        #pragma unroll
        for (int o = 4; o; o >>= 1) r += __shfl_xor_sync(0xFFu, r, o);
        if (threadIdx.x == 0) red[0] = r;
    }
    __syncthreads();
    float out = red[0];
    __syncthreads();
    return out;
}

__constant__ float c_bb[3][3] = {
    {-0.525f, 1.363f, 0.0f},
    { 0.0f,   0.0f,   0.0f},
    { 1.526f, 0.0f,   0.0f}
};

__global__ __launch_bounds__(256, 4)
void ln_head_kernel(const float* __restrict__ ln_g,
                    const float* __restrict__ ln_b,
                    const float* __restrict__ w2,
                    const float* __restrict__ b2,
                    const float* __restrict__ affine,
                    const int*   __restrict__ mask,
                    float* __restrict__ out)
{
    const int row = blockIdx.x;
    const int tid = threadIdx.x;
    constexpr int T = 256;
    constexpr int PER2 = D_DIM / (2 * T);   // 3 float2 per thread

    __shared__ float sh[D_DIM];
    __shared__ float red[32];
    __shared__ float p[12];

    const float2* h2 = (const float2*)(g_h + (size_t)row * D_DIM);

    float2 l[PER2];
    float s = 0.0f;
    #pragma unroll
    for (int i = 0; i < PER2; i++) {
        l[i] = h2[tid + i * T];
        s += l[i].x + l[i].y;
    }
    const float mu = block_reduce_sum(s, red) * (1.0f / D_DIM);

    float s2 = 0.0f;
    #pragma unroll
    for (int i = 0; i < PER2; i++) {
        float dx = l[i].x - mu, dy = l[i].y - mu;
        s2 += dx * dx + dy * dy;
    }
    const float var = block_reduce_sum(s2, red) * (1.0f / D_DIM);
    const float inv = rsqrtf(var + 1e-5f);

    const float2* g2 = (const float2*)ln_g;
    const float2* be2 = (const float2*)ln_b;
    #pragma unroll
    for (int i = 0; i < PER2; i++) {
        const int idx = tid + i * T;
        float2 g = g2[idx], b = be2[idx];
        sh[2*idx]   = (l[i].x - mu) * inv * g.x + b.x;
        sh[2*idx+1] = (l[i].y - mu) * inv * g.y + b.y;
    }
    __syncthreads();

    const int warp = tid >> 5, lane = tid & 31;
    for (int o = warp; o < NGEO; o += 8) {
        const float4* wr4 = (const float4*)(w2 + (size_t)o * D_DIM);
        const float4* sh4 = (const float4*)sh;
        float acc = 0.0f;
        #pragma unroll 4
        for (int d4 = lane; d4 < D_DIM / 4; d4 += 32) {
            float4 w = wr4[d4];
            float4 h = sh4[d4];
            acc = fmaf(w.x, h.x, acc);
            acc = fmaf(w.y, h.y, acc);
            acc = fmaf(w.z, h.z, acc);
            acc = fmaf(w.w, h.w, acc);
        }
        #pragma unroll
        for (int off = 16; off; off >>= 1) acc += __shfl_xor_sync(0xFFFFFFFFu, acc, off);
        if (lane == 0) p[o] = acc + b2[o];
    }
    __syncthreads();

    if (tid == 0) {
        float trans[3], xv[3], yv[3];
        #pragma unroll
        for (int i = 0; i < 3; i++) {
            trans[i] = p[i] * 10.0f;
            xv[i]    = p[3 + i];
            yv[i]    = p[6 + i];
        }
        float xn = sqrtf(xv[0]*xv[0] + xv[1]*xv[1] + xv[2]*xv[2]) + 1e-5f;
        float yn = sqrtf(yv[0]*yv[0] + yv[1]*yv[1] + yv[2]*yv[2]) + 1e-5f;
        #pragma unroll
        for (int i = 0; i < 3; i++) { xv[i] /= xn; yv[i] /= yn; }

        float ax[3] = { -xv[0], -xv[1], -xv[2] };
        float n0 = rsqrtf(ax[0]*ax[0] + ax[1]*ax[1] + ax[2]*ax[2] + 1e-12f);
        float e0[3] = { ax[0]*n0, ax[1]*n0, ax[2]*n0 };
        float c = e0[0]*yv[0] + e0[1]*yv[1] + e0[2]*yv[2];
        float e1[3] = { yv[0] - e0[0]*c, yv[1] - e0[1]*c, yv[2] - e0[2]*c };
        float n1 = rsqrtf(e1[0]*e1[0] + e1[1]*e1[1] + e1[2]*e1[2] + 1e-12f);
        e1[0] *= n1; e1[1] *= n1; e1[2] *= n1;
        float e2[3] = { e0[1]*e1[2] - e0[2]*e1[1],
                        e0[2]*e1[0] - e0[0]*e1[2],
                        e0[0]*e1[1] - e0[1]*e1[0] };

        float Ru[3][3] = {
            { e0[0], e1[0], e2[0] },
            { e0[1], e1[1], e2[1] },
            { e0[2], e1[2], e2[2] }
        };
        float tu[3] = { trans[0], trans[1], trans[2] };

        const bool m = (mask[row] != 0);
        if (!m) {
            #pragma unroll
            for (int i = 0; i < 3; i++) {
                #pragma unroll
                for (int j = 0; j < 3; j++) Ru[i][j] = (i == j) ? 1.0f : 0.0f;
                tu[i] = 0.0f;
            }
        }

        const float* af = affine + (size_t)row * 12;
        float R0[3][3], t0[3];
        #pragma unroll
        for (int i = 0; i < 3; i++) {
            #pragma unroll
            for (int j = 0; j < 3; j++) R0[i][j] = af[i * 3 + j];
            t0[i] = af[9 + i];
        }

        float R[3][3], tt[3];
        #pragma unroll
        for (int i = 0; i < 3; i++) {
            #pragma unroll
            for (int j = 0; j < 3; j++) {
                float acc = 0.0f;
                #pragma unroll
                for (int k = 0; k < 3; k++) acc = fmaf(R0[i][k], Ru[k][j], acc);
                R[i][j] = acc;
            }
            float ta = t0[i];
            #pragma unroll
            for (int j = 0; j < 3; j++) ta = fmaf(R0[i][j], tu[j], ta);
            tt[i] = ta;
        }

        float* ao = out + (size_t)row * 12;
        #pragma unroll
        for (int i = 0; i < 3; i++)
            #pragma unroll
            for (int j = 0; j < 3; j++) ao[i * 3 + j] = R[i][j];
        #pragma unroll
        for (int i = 0; i < 3; i++) ao[9 + i] = tt[i];

        float* po = out + (size_t)M_TOT * 12 + (size_t)row * 9;
        #pragma unroll
        for (int a = 0; a < 3; a++) {
            #pragma unroll
            for (int i = 0; i < 3; i++) {
                float v = tt[i];
                #pragma unroll
                for (int j = 0; j < 3; j++) v = fmaf(R[i][j], c_bb[a][j], v);
                po[a * 3 + i] = v;
            }
        }
    }
}

// ---------------------------------------------------------------------------
extern "C" void kernel_launch(void* const* d_in, const int* in_sizes, int n_in,
                              void* d_out, int out_size)
{
    const float* x      = (const float*)d_in[0];
    const float* affine = (const float*)d_in[1];
    const int*   amask  = (const int*)  d_in[2];
    const float* w1     = (const float*)d_in[3];
    const float* b1     = (const float*)d_in[4];
    const float* ln_g   = (const float*)d_in[5];
    const float* ln_b   = (const float*)d_in[6];
    const float* w2     = (const float*)d_in[7];
    const float* b2     = (const float*)d_in[8];
    float* out = (float*)d_out;

    cudaFuncSetAttribute(gemm_mma_kernel,
                         cudaFuncAttributeMaxDynamicSharedMemorySize, SMEM_BYTES);

    conv_x_kernel<<<4096, 256>>>(x);
    conv_w_kernel<<<2304, 256>>>(w1);

    dim3 grid(D_DIM / TN, M_TOT / TM);   // (12, 32)
    gemm_mma_kernel<<<grid, 256, SMEM_BYTES>>>(b1);

    ln_head_kernel<<<M_TOT, 256>>>(ln_g, ln_b, w2, b2, affine, amask, out);
}

// round 6
// speedup vs baseline: 3.7002x; 1.0435x over previous
#include <cuda_runtime.h>
#include <cuda_bf16.h>
#include <math.h>
#include <cstdint>

#define D_DIM 1536
#define M_TOT 4096          // B*L
#define K2    3072          // 2 * D_DIM : [hi | lo]
#define NCH   24            // 1536 / 64
#define TM 128
#define TN 128
#define NTILES ((M_TOT / TM) * (D_DIM / TN))   // 32 * 12 = 384
#define NGEO 9

// scratch (device globals — no allocation allowed)
__device__ __nv_bfloat16 g_A[(size_t)M_TOT * K2];   // [M, K2] = [hi | lo]
__device__ __nv_bfloat16 g_B[(size_t)D_DIM * K2];   // [N, K2] = [hi | lo]
__device__ float         g_h[(size_t)M_TOT * D_DIM];

// ---------------------------------------------------------------------------
// split-to-bf16 conversion kernels (vectorized: float4 in, 8B bf16x4 out)
// ---------------------------------------------------------------------------
__device__ __forceinline__ uint2 split_hi(float4 v) {
    __nv_bfloat162 h01 = __nv_bfloat162(__float2bfloat16(v.x), __float2bfloat16(v.y));
    __nv_bfloat162 h23 = __nv_bfloat162(__float2bfloat16(v.z), __float2bfloat16(v.w));
    uint2 r; r.x = *(uint32_t*)&h01; r.y = *(uint32_t*)&h23; return r;
}
__device__ __forceinline__ uint2 split_lo(float4 v) {
    float lx = v.x - __bfloat162float(__float2bfloat16(v.x));
    float ly = v.y - __bfloat162float(__float2bfloat16(v.y));
    float lz = v.z - __bfloat162float(__float2bfloat16(v.z));
    float lw = v.w - __bfloat162float(__float2bfloat16(v.w));
    __nv_bfloat162 l01 = __nv_bfloat162(__float2bfloat16(lx), __float2bfloat16(ly));
    __nv_bfloat162 l23 = __nv_bfloat162(__float2bfloat16(lz), __float2bfloat16(lw));
    uint2 r; r.x = *(uint32_t*)&l01; r.y = *(uint32_t*)&l23; return r;
}

__global__ void conv_x_kernel(const float* __restrict__ x)
{
    const int i = blockIdx.x * blockDim.x + threadIdx.x;     // float4 index
    if (i >= M_TOT * D_DIM / 4) return;
    float4 v = ((const float4*)x)[i];
    const int row = (i * 4) / D_DIM, d = (i * 4) % D_DIM;
    uint2* hp = (uint2*)(g_A + (size_t)row * K2 + d);
    uint2* lp = (uint2*)(g_A + (size_t)row * K2 + D_DIM + d);
    *hp = split_hi(v);
    *lp = split_lo(v);
}

__global__ void conv_w_kernel(const float* __restrict__ w1)
{
    const int i = blockIdx.x * blockDim.x + threadIdx.x;
    if (i >= D_DIM * D_DIM / 4) return;
    float4 v = ((const float4*)w1)[i];
    const int row = (i * 4) / D_DIM, d = (i * 4) % D_DIM;
    uint2* hp = (uint2*)(g_B + (size_t)row * K2 + d);
    uint2* lp = (uint2*)(g_B + (size_t)row * K2 + D_DIM + d);
    *hp = split_hi(v);
    *lp = split_lo(v);
}

// ---------------------------------------------------------------------------
// Persistent HMMA GEMM with in-register hi/lo sharing:
//   acc += A_hi·B_hi + A_lo·B_hi + A_hi·B_lo      (lo·lo dropped, O(2^-18))
// ---------------------------------------------------------------------------
#define SWZ(o) ((o) ^ (((o) >> 3) & 0x70))

__device__ __forceinline__ uint32_t s2u(const void* p) {
    uint32_t a;
    asm("{ .reg .u64 t; cvta.to.shared.u64 t, %1; cvt.u32.u64 %0, t; }"
        : "=r"(a) : "l"(p));
    return a;
}
__device__ __forceinline__ void cp16(uint32_t dst, const void* src) {
    asm volatile("cp.async.cg.shared.global [%0], [%1], 16;\n"
                 :: "r"(dst), "l"(src));
}
__device__ __forceinline__ void ldm4(uint32_t* r, uint32_t addr) {
    asm volatile("ldmatrix.sync.aligned.m8n8.x4.shared.b16 {%0,%1,%2,%3}, [%4];"
                 : "=r"(r[0]), "=r"(r[1]), "=r"(r[2]), "=r"(r[3]) : "r"(addr));
}
__device__ __forceinline__ void mma16816(float* c, const uint32_t* a, const uint32_t* b) {
    asm volatile("mma.sync.aligned.m16n8k16.row.col.f32.bf16.bf16.f32 "
                 "{%0,%1,%2,%3}, {%4,%5,%6,%7}, {%8,%9}, {%0,%1,%2,%3};"
                 : "+f"(c[0]), "+f"(c[1]), "+f"(c[2]), "+f"(c[3])
                 : "r"(a[0]), "r"(a[1]), "r"(a[2]), "r"(a[3]),
                   "r"(b[0]), "r"(b[1]));
}

static constexpr int TILE_B  = TM * 128;               // 16 KB per tile
static constexpr int STAGE_B = 4 * TILE_B;             // AH, AL, BH, BL = 64 KB
static constexpr int SMEM_BYTES = 2 * STAGE_B + 1024;

__global__ __launch_bounds__(256)
void gemm_mma_kernel(const float* __restrict__ b1)
{
    extern __shared__ char smem[];
    const uint32_t sb = (s2u(smem) + 1023) & ~1023u;

    const int tid  = threadIdx.x;
    const int wid  = tid >> 5, lane = tid & 31;
    const int wm   = wid & 1;          // 2 warps in M
    const int wn   = wid >> 1;         // 4 warps in N

    const uint32_t STG[2] = { sb, sb + STAGE_B };

    // per-lane ldmatrix address components (tile-independent)
    uint32_t a_row[4], a_xr[4];
    #pragma unroll
    for (int i = 0; i < 4; i++) {
        int row = wm * 64 + i * 16 + (lane & 15);
        a_row[i] = row * 128;
        a_xr[i]  = (row & 7) << 4;
    }
    const uint32_t a_kh = (lane >> 4) * 16;

    uint32_t b_row[2], b_xr[2];
    #pragma unroll
    for (int j2 = 0; j2 < 2; j2++) {
        int row = wn * 32 + j2 * 16 + (lane & 7) + ((lane >> 4) & 1) * 8;
        b_row[j2] = row * 128;
        b_xr[j2]  = (row & 7) << 4;
    }
    const uint32_t b_kh = ((lane >> 3) & 1) * 16;

    // loader lane mapping (tile-independent parts)
    const int l_r  = (tid * 8) >> 3 >> 0;  // dummy to silence
    (void)l_r;

    for (int t = blockIdx.x; t < NTILES; t += gridDim.x) {
        const int bm = (t / (D_DIM / TN)) * TM;
        const int bn = (t % (D_DIM / TN)) * TN;

        auto load_stage = [&](int s, int k0) {
            const uint32_t st = STG[s];
            #pragma unroll
            for (int i = 0; i < 4; i++) {
                int u  = tid + i * 256;
                int r  = u >> 3, c8 = u & 7;
                uint32_t dsw = SWZ(r * 128 + c8 * 16);
                const __nv_bfloat16* arow = g_A + (size_t)(bm + r) * K2 + k0 + c8 * 8;
                const __nv_bfloat16* brow = g_B + (size_t)(bn + r) * K2 + k0 + c8 * 8;
                cp16(st              + dsw, arow);
                cp16(st +     TILE_B + dsw, arow + D_DIM);
                cp16(st + 2 * TILE_B + dsw, brow);
                cp16(st + 3 * TILE_B + dsw, brow + D_DIM);
            }
        };

        float acc[4][4][4] = {};

        load_stage(0, 0);
        asm volatile("cp.async.commit_group;" ::: "memory");

        for (int ch = 0; ch < NCH; ch++) {
            const int cur = ch & 1, nxt = cur ^ 1;
            if (ch + 1 < NCH) {
                load_stage(nxt, (ch + 1) * 64);
                asm volatile("cp.async.commit_group;" ::: "memory");
                asm volatile("cp.async.wait_group 1;" ::: "memory");
            } else {
                asm volatile("cp.async.wait_group 0;" ::: "memory");
            }
            __syncthreads();

            const uint32_t AH = STG[cur];
            const uint32_t AL = AH + TILE_B;
            const uint32_t BH = AH + 2 * TILE_B;
            const uint32_t BL = AH + 3 * TILE_B;

            #pragma unroll
            for (int ks = 0; ks < 4; ks++) {
                const uint32_t kb = ks * 32;
                uint32_t ah[4][4], al[4][4], bh[2][4], bl[2][4];
                #pragma unroll
                for (int i = 0; i < 4; i++) {
                    uint32_t off = a_row[i] + ((kb + a_kh) ^ a_xr[i]);
                    ldm4(ah[i], AH + off);
                    ldm4(al[i], AL + off);
                }
                #pragma unroll
                for (int j2 = 0; j2 < 2; j2++) {
                    uint32_t off = b_row[j2] + ((kb + b_kh) ^ b_xr[j2]);
                    ldm4(bh[j2], BH + off);
                    ldm4(bl[j2], BL + off);
                }
                #pragma unroll
                for (int i = 0; i < 4; i++) {
                    #pragma unroll
                    for (int j = 0; j < 4; j++) {
                        const uint32_t* bhp = bh[j >> 1] + (j & 1) * 2;
                        const uint32_t* blp = bl[j >> 1] + (j & 1) * 2;
                        mma16816(acc[i][j], ah[i], bhp);
                        mma16816(acc[i][j], al[i], bhp);
                        mma16816(acc[i][j], ah[i], blp);
                    }
                }
            }
            __syncthreads();
        }

        // epilogue: bias + exact GELU
        const int r0 = lane >> 2;
        const int c0 = (lane & 3) * 2;
        #pragma unroll
        for (int i = 0; i < 4; i++) {
            const int m0 = bm + wm * 64 + i * 16 + r0;
            #pragma unroll
            for (int j = 0; j < 4; j++) {
                const int col = bn + wn * 32 + j * 8 + c0;
                const float bb0 = __ldg(&b1[col]);
                const float bb1 = __ldg(&b1[col + 1]);
                #pragma unroll
                for (int half = 0; half < 2; half++) {
                    const int m = m0 + half * 8;
                    float v0 = acc[i][j][half * 2 + 0] + bb0;
                    float v1 = acc[i][j][half * 2 + 1] + bb1;
                    float g0 = 0.5f * v0 * (1.0f + erff(v0 * 0.70710678118654752440f));
                    float g1 = 0.5f * v1 * (1.0f + erff(v1 * 0.70710678118654752440f));
                    *(float2*)(g_h + (size_t)m * D_DIM + col) = make_float2(g0, g1);
                }
            }
        }
    }
}

// ---------------------------------------------------------------------------
// Kernel B: 4 tokens per block — LN -> p[0:9] -> geometry.  w2 reuse x4.
// ---------------------------------------------------------------------------
__constant__ float c_bb[3][3] = {
    {-0.525f, 1.363f, 0.0f},
    { 0.0f,   0.0f,   0.0f},
    { 1.526f, 0.0f,   0.0f}
};

__global__ __launch_bounds__(256)
void ln_head_kernel(const float* __restrict__ ln_g,
                    const float* __restrict__ ln_b,
                    const float* __restrict__ w2,
                    const float* __restrict__ b2,
                    const float* __restrict__ affine,
                    const int*   __restrict__ mask,
                    float* __restrict__ out)
{
    const int tid  = threadIdx.x;
    const int wid  = tid >> 5, lane = tid & 31;
    const int sub  = tid >> 6;          // 0..3 : row within block
    const int st   = tid & 63;          // 0..63 : thread within row group
    const int row0 = blockIdx.x * 4;
    const int row  = row0 + sub;

    __shared__ float sh[4][D_DIM];
    __shared__ float red[16];
    __shared__ float pbuf[4][12];

    // ---- LN: 64 threads per row, 24 floats (6 float4) each ----
    const float4* h4 = (const float4*)(g_h + (size_t)row * D_DIM);
    float4 l[6];
    float s = 0.0f;
    #pragma unroll
    for (int j = 0; j < 6; j++) {
        l[j] = h4[st + j * 64];
        s += (l[j].x + l[j].y) + (l[j].z + l[j].w);
    }
    #pragma unroll
    for (int o = 16; o; o >>= 1) s += __shfl_xor_sync(0xFFFFFFFFu, s, o);
    if (lane == 0) red[wid] = s;
    __syncthreads();
    const float mu = (red[sub * 2] + red[sub * 2 + 1]) * (1.0f / D_DIM);

    float s2 = 0.0f;
    #pragma unroll
    for (int j = 0; j < 6; j++) {
        float dx = l[j].x - mu, dy = l[j].y - mu, dz = l[j].z - mu, dw = l[j].w - mu;
        s2 += dx * dx + dy * dy + dz * dz + dw * dw;
    }
    #pragma unroll
    for (int o = 16; o; o >>= 1) s2 += __shfl_xor_sync(0xFFFFFFFFu, s2, o);
    __syncthreads();                      // red pass-1 reads complete
    if (lane == 0) red[wid] = s2;
    __syncthreads();
    const float var = (red[sub * 2] + red[sub * 2 + 1]) * (1.0f / D_DIM);
    const float inv = rsqrtf(var + 1e-5f);

    const float4* g4 = (const float4*)ln_g;
    const float4* b4 = (const float4*)ln_b;
    #pragma unroll
    for (int j = 0; j < 6; j++) {
        const int idx = st + j * 64;
        float4 g = g4[idx], b = b4[idx];
        float4 r;
        r.x = (l[j].x - mu) * inv * g.x + b.x;
        r.y = (l[j].y - mu) * inv * g.y + b.y;
        r.z = (l[j].z - mu) * inv * g.z + b.z;
        r.w = (l[j].w - mu) * inv * g.w + b.w;
        ((float4*)sh[sub])[idx] = r;
    }
    __syncthreads();

    // ---- dot: warp w handles outputs o = w, w+8 (<9); 4 rows share w2 loads ----
    for (int o = wid; o < NGEO; o += 8) {
        const float4* w4 = (const float4*)(w2 + (size_t)o * D_DIM);
        float a0 = 0.f, a1 = 0.f, a2 = 0.f, a3 = 0.f;
        #pragma unroll 4
        for (int d4 = lane; d4 < D_DIM / 4; d4 += 32) {
            float4 w = w4[d4];
            float4 h0 = ((const float4*)sh[0])[d4];
            float4 h1 = ((const float4*)sh[1])[d4];
            float4 h2 = ((const float4*)sh[2])[d4];
            float4 h3 = ((const float4*)sh[3])[d4];
            a0 = fmaf(w.x, h0.x, fmaf(w.y, h0.y, fmaf(w.z, h0.z, fmaf(w.w, h0.w, a0))));
            a1 = fmaf(w.x, h1.x, fmaf(w.y, h1.y, fmaf(w.z, h1.z, fmaf(w.w, h1.w, a1))));
            a2 = fmaf(w.x, h2.x, fmaf(w.y, h2.y, fmaf(w.z, h2.z, fmaf(w.w, h2.w, a2))));
            a3 = fmaf(w.x, h3.x, fmaf(w.y, h3.y, fmaf(w.z, h3.z, fmaf(w.w, h3.w, a3))));
        }
        #pragma unroll
        for (int off = 16; off; off >>= 1) {
            a0 += __shfl_xor_sync(0xFFFFFFFFu, a0, off);
            a1 += __shfl_xor_sync(0xFFFFFFFFu, a1, off);
            a2 += __shfl_xor_sync(0xFFFFFFFFu, a2, off);
            a3 += __shfl_xor_sync(0xFFFFFFFFu, a3, off);
        }
        if (lane == 0) {
            const float bb = b2[o];
            pbuf[0][o] = a0 + bb;
            pbuf[1][o] = a1 + bb;
            pbuf[2][o] = a2 + bb;
            pbuf[3][o] = a3 + bb;
        }
    }
    __syncthreads();

    // ---- geometry: threads 0..3, one row each ----
    if (tid < 4) {
        const int r = row0 + tid;
        const float* p = pbuf[tid];
        float trans[3], xv[3], yv[3];
        #pragma unroll
        for (int i = 0; i < 3; i++) {
            trans[i] = p[i] * 10.0f;
            xv[i]    = p[3 + i];
            yv[i]    = p[6 + i];
        }
        float xn = sqrtf(xv[0]*xv[0] + xv[1]*xv[1] + xv[2]*xv[2]) + 1e-5f;
        float yn = sqrtf(yv[0]*yv[0] + yv[1]*yv[1] + yv[2]*yv[2]) + 1e-5f;
        #pragma unroll
        for (int i = 0; i < 3; i++) { xv[i] /= xn; yv[i] /= yn; }

        float ax[3] = { -xv[0], -xv[1], -xv[2] };
        float n0 = rsqrtf(ax[0]*ax[0] + ax[1]*ax[1] + ax[2]*ax[2] + 1e-12f);
        float e0[3] = { ax[0]*n0, ax[1]*n0, ax[2]*n0 };
        float c = e0[0]*yv[0] + e0[1]*yv[1] + e0[2]*yv[2];
        float e1[3] = { yv[0] - e0[0]*c, yv[1] - e0[1]*c, yv[2] - e0[2]*c };
        float n1 = rsqrtf(e1[0]*e1[0] + e1[1]*e1[1] + e1[2]*e1[2] + 1e-12f);
        e1[0] *= n1; e1[1] *= n1; e1[2] *= n1;
        float e2[3] = { e0[1]*e1[2] - e0[2]*e1[1],
                        e0[2]*e1[0] - e0[0]*e1[2],
                        e0[0]*e1[1] - e0[1]*e1[0] };

        float Ru[3][3] = {
            { e0[0], e1[0], e2[0] },
            { e0[1], e1[1], e2[1] },
            { e0[2], e1[2], e2[2] }
        };
        float tu[3] = { trans[0], trans[1], trans[2] };

        if (mask[r] == 0) {
            #pragma unroll
            for (int i = 0; i < 3; i++) {
                #pragma unroll
                for (int j = 0; j < 3; j++) Ru[i][j] = (i == j) ? 1.0f : 0.0f;
                tu[i] = 0.0f;
            }
        }

        const float* af = affine + (size_t)r * 12;
        float R0[3][3], t0[3];
        #pragma unroll
        for (int i = 0; i < 3; i++) {
            #pragma unroll
            for (int j = 0; j < 3; j++) R0[i][j] = af[i * 3 + j];
            t0[i] = af[9 + i];
        }

        float R[3][3], tt[3];
        #pragma unroll
        for (int i = 0; i < 3; i++) {
            #pragma unroll
            for (int j = 0; j < 3; j++) {
                float a = 0.0f;
                #pragma unroll
                for (int k = 0; k < 3; k++) a = fmaf(R0[i][k], Ru[k][j], a);
                R[i][j] = a;
            }
            float ta = t0[i];
            #pragma unroll
            for (int j = 0; j < 3; j++) ta = fmaf(R0[i][j], tu[j], ta);
            tt[i] = ta;
        }

        float* ao = out + (size_t)r * 12;
        #pragma unroll
        for (int i = 0; i < 3; i++)
            #pragma unroll
            for (int j = 0; j < 3; j++) ao[i * 3 + j] = R[i][j];
        #pragma unroll
        for (int i = 0; i < 3; i++) ao[9 + i] = tt[i];

        float* po = out + (size_t)M_TOT * 12 + (size_t)r * 9;
        #pragma unroll
        for (int a = 0; a < 3; a++) {
            #pragma unroll
            for (int i = 0; i < 3; i++) {
                float v = tt[i];
                #pragma unroll
                for (int j = 0; j < 3; j++) v = fmaf(R[i][j], c_bb[a][j], v);
                po[a * 3 + i] = v;
            }
        }
    }
}

// ---------------------------------------------------------------------------
extern "C" void kernel_launch(void* const* d_in, const int* in_sizes, int n_in,
                              void* d_out, int out_size)
{
    const float* x      = (const float*)d_in[0];
    const float* affine = (const float*)d_in[1];
    const int*   amask  = (const int*)  d_in[2];
    const float* w1     = (const float*)d_in[3];
    const float* b1     = (const float*)d_in[4];
    const float* ln_g   = (const float*)d_in[5];
    const float* ln_b   = (const float*)d_in[6];
    const float* w2     = (const float*)d_in[7];
    const float* b2     = (const float*)d_in[8];
    float* out = (float*)d_out;

    cudaFuncSetAttribute(gemm_mma_kernel,
                         cudaFuncAttributeMaxDynamicSharedMemorySize, SMEM_BYTES);

    int sms = 148;
    cudaDeviceGetAttribute(&sms, cudaDevAttrMultiProcessorCount, 0);

    conv_x_kernel<<<(M_TOT * D_DIM / 4 + 255) / 256, 256>>>(x);
    conv_w_kernel<<<(D_DIM * D_DIM / 4 + 255) / 256, 256>>>(w1);

    gemm_mma_kernel<<<sms, 256, SMEM_BYTES>>>(b1);

    ln_head_kernel<<<M_TOT / 4, 256>>>(ln_g, ln_b, w2, b2, affine, amask, out);
}